// round 2
// baseline (speedup 1.0000x reference)
#include <cuda_runtime.h>
#include <math.h>

// Problem constants
#define BB 4
#define SS 4096
#define EE 512

// Scratch (allocation-free rule: __device__ globals)
__device__ float g_q[(size_t)BB * SS * EE];
__device__ float g_k[(size_t)BB * SS * EE];
__device__ float g_v[(size_t)BB * SS * EE];
__device__ float g_scores[(size_t)BB * SS * SS];

// ---------------------------------------------------------------------------
// Tiled fp32 GEMM: C = A @ op(B) (+ bias), 128x128 tile, BK=16, 256 threads,
// 8x8 per-thread micro-tile, register-staged double buffering.
//   TRANSB=true : B is [N,K] row-major, C[m,n] = sum_k A[m,k]*B[n,k]
//   TRANSB=false: B is [K,N] row-major, C[m,n] = sum_k A[m,k]*B[k,n]
// All dims must be multiples of the tile sizes (true for this problem).
// ---------------------------------------------------------------------------
template <bool TRANSB, bool BIAS>
__global__ __launch_bounds__(256) void sgemm_kernel(
    const float* __restrict__ A, const float* __restrict__ Bm,
    const float* __restrict__ bias, float* __restrict__ C,
    int M, int N, int K,
    long long strideA, long long strideB, long long strideC)
{
    constexpr int BM = 128, BN = 128, BK = 16;

    const long long bz = blockIdx.z;
    A  += bz * strideA;
    Bm += bz * strideB;
    C  += bz * strideC;

    __shared__ __align__(16) float As[2][BK][BM + 4];
    __shared__ __align__(16) float Bs[2][BK][BN + 4];

    const int tid = threadIdx.x;
    const int tx = tid & 15;        // 0..15 -> column group
    const int ty = tid >> 4;        // 0..15 -> row group
    const int row0 = blockIdx.y * BM;
    const int col0 = blockIdx.x * BN;

    // --- load index precompute ---
    // A tile (128 rows x 16 k): 512 float4, thread handles f=tid and f=tid+256
    const int a_row = tid >> 2;          // 0..63 (second load adds 64)
    const int a_kc  = (tid & 3) * 4;     // k offset 0,4,8,12
    // B tile TRANSB (128 n-rows x 16 k): same mapping as A
    // B tile NN (16 k-rows x 128 n): 512 float4: f=tid -> krow=tid>>5, nc=(tid&31)*4
    const int b_kr = tid >> 5;           // 0..7 (second load adds 8)
    const int b_nc = (tid & 31) * 4;

    float acc[8][8];
#pragma unroll
    for (int i = 0; i < 8; i++)
#pragma unroll
        for (int j = 0; j < 8; j++) acc[i][j] = 0.0f;

    const int nk = K / BK;

    // ---- helpers (inlined manually) ----
    float4 a0, a1, b0, b1;

    // load tile kt=0
    {
        const int k0 = 0;
        a0 = *(const float4*)(A + (long long)(row0 + a_row) * K + k0 + a_kc);
        a1 = *(const float4*)(A + (long long)(row0 + a_row + 64) * K + k0 + a_kc);
        if (TRANSB) {
            b0 = *(const float4*)(Bm + (long long)(col0 + a_row) * K + k0 + a_kc);
            b1 = *(const float4*)(Bm + (long long)(col0 + a_row + 64) * K + k0 + a_kc);
        } else {
            b0 = *(const float4*)(Bm + (long long)(k0 + b_kr) * N + col0 + b_nc);
            b1 = *(const float4*)(Bm + (long long)(k0 + b_kr + 8) * N + col0 + b_nc);
        }
        // store buf 0
        As[0][a_kc + 0][a_row] = a0.x;  As[0][a_kc + 1][a_row] = a0.y;
        As[0][a_kc + 2][a_row] = a0.z;  As[0][a_kc + 3][a_row] = a0.w;
        As[0][a_kc + 0][a_row + 64] = a1.x;  As[0][a_kc + 1][a_row + 64] = a1.y;
        As[0][a_kc + 2][a_row + 64] = a1.z;  As[0][a_kc + 3][a_row + 64] = a1.w;
        if (TRANSB) {
            Bs[0][a_kc + 0][a_row] = b0.x;  Bs[0][a_kc + 1][a_row] = b0.y;
            Bs[0][a_kc + 2][a_row] = b0.z;  Bs[0][a_kc + 3][a_row] = b0.w;
            Bs[0][a_kc + 0][a_row + 64] = b1.x;  Bs[0][a_kc + 1][a_row + 64] = b1.y;
            Bs[0][a_kc + 2][a_row + 64] = b1.z;  Bs[0][a_kc + 3][a_row + 64] = b1.w;
        } else {
            *(float4*)&Bs[0][b_kr][b_nc]     = b0;
            *(float4*)&Bs[0][b_kr + 8][b_nc] = b1;
        }
    }
    __syncthreads();

    for (int kt = 0; kt < nk; kt++) {
        const int cur = kt & 1;
        const int nxt = cur ^ 1;
        const bool more = (kt + 1) < nk;

        if (more) {
            const int k0 = (kt + 1) * BK;
            a0 = *(const float4*)(A + (long long)(row0 + a_row) * K + k0 + a_kc);
            a1 = *(const float4*)(A + (long long)(row0 + a_row + 64) * K + k0 + a_kc);
            if (TRANSB) {
                b0 = *(const float4*)(Bm + (long long)(col0 + a_row) * K + k0 + a_kc);
                b1 = *(const float4*)(Bm + (long long)(col0 + a_row + 64) * K + k0 + a_kc);
            } else {
                b0 = *(const float4*)(Bm + (long long)(k0 + b_kr) * N + col0 + b_nc);
                b1 = *(const float4*)(Bm + (long long)(k0 + b_kr + 8) * N + col0 + b_nc);
            }
        }

#pragma unroll
        for (int kk = 0; kk < BK; kk++) {
            float ar[8], br[8];
            *(float4*)&ar[0] = *(const float4*)&As[cur][kk][ty * 8];
            *(float4*)&ar[4] = *(const float4*)&As[cur][kk][ty * 8 + 4];
            *(float4*)&br[0] = *(const float4*)&Bs[cur][kk][tx * 8];
            *(float4*)&br[4] = *(const float4*)&Bs[cur][kk][tx * 8 + 4];
#pragma unroll
            for (int i = 0; i < 8; i++)
#pragma unroll
                for (int j = 0; j < 8; j++)
                    acc[i][j] = fmaf(ar[i], br[j], acc[i][j]);
        }

        if (more) {
            As[nxt][a_kc + 0][a_row] = a0.x;  As[nxt][a_kc + 1][a_row] = a0.y;
            As[nxt][a_kc + 2][a_row] = a0.z;  As[nxt][a_kc + 3][a_row] = a0.w;
            As[nxt][a_kc + 0][a_row + 64] = a1.x;  As[nxt][a_kc + 1][a_row + 64] = a1.y;
            As[nxt][a_kc + 2][a_row + 64] = a1.z;  As[nxt][a_kc + 3][a_row + 64] = a1.w;
            if (TRANSB) {
                Bs[nxt][a_kc + 0][a_row] = b0.x;  Bs[nxt][a_kc + 1][a_row] = b0.y;
                Bs[nxt][a_kc + 2][a_row] = b0.z;  Bs[nxt][a_kc + 3][a_row] = b0.w;
                Bs[nxt][a_kc + 0][a_row + 64] = b1.x;  Bs[nxt][a_kc + 1][a_row + 64] = b1.y;
                Bs[nxt][a_kc + 2][a_row + 64] = b1.z;  Bs[nxt][a_kc + 3][a_row + 64] = b1.w;
            } else {
                *(float4*)&Bs[nxt][b_kr][b_nc]     = b0;
                *(float4*)&Bs[nxt][b_kr + 8][b_nc] = b1;
            }
            __syncthreads();
        }
    }

    // epilogue
    float bv[8];
    if (BIAS) {
#pragma unroll
        for (int j = 0; j < 8; j++) bv[j] = bias[col0 + tx * 8 + j];
    }
#pragma unroll
    for (int i = 0; i < 8; i++) {
        const long long r = row0 + ty * 8 + i;
#pragma unroll
        for (int j = 0; j < 8; j += 4) {
            float4 v;
            v.x = acc[i][j + 0]; v.y = acc[i][j + 1];
            v.z = acc[i][j + 2]; v.w = acc[i][j + 3];
            if (BIAS) { v.x += bv[j]; v.y += bv[j + 1]; v.z += bv[j + 2]; v.w += bv[j + 3]; }
            *(float4*)(C + r * N + col0 + tx * 8 + j) = v;
        }
    }
}

// ---------------------------------------------------------------------------
// In-place numerically-stable softmax over rows of length 4096.
// One 256-thread block per row; each thread holds 16 elements in registers.
// ---------------------------------------------------------------------------
__global__ __launch_bounds__(256) void softmax_kernel(float* __restrict__ scores)
{
    const long long row = blockIdx.x;
    float4* p4 = (float4*)(scores + row * (long long)SS);
    const int tid = threadIdx.x;
    const int lane = tid & 31;
    const int wid = tid >> 5;

    float4 r[4];
    float m = -1e30f;
#pragma unroll
    for (int i = 0; i < 4; i++) {
        r[i] = p4[tid + 256 * i];
        m = fmaxf(m, fmaxf(fmaxf(r[i].x, r[i].y), fmaxf(r[i].z, r[i].w)));
    }
#pragma unroll
    for (int o = 16; o > 0; o >>= 1) m = fmaxf(m, __shfl_xor_sync(0xffffffffu, m, o));

    __shared__ float red[8];
    if (lane == 0) red[wid] = m;
    __syncthreads();
    m = red[0];
#pragma unroll
    for (int i = 1; i < 8; i++) m = fmaxf(m, red[i]);

    float s = 0.0f;
#pragma unroll
    for (int i = 0; i < 4; i++) {
        r[i].x = __expf(r[i].x - m);
        r[i].y = __expf(r[i].y - m);
        r[i].z = __expf(r[i].z - m);
        r[i].w = __expf(r[i].w - m);
        s += r[i].x + r[i].y + r[i].z + r[i].w;
    }
#pragma unroll
    for (int o = 16; o > 0; o >>= 1) s += __shfl_xor_sync(0xffffffffu, s, o);

    __shared__ float red2[8];
    if (lane == 0) red2[wid] = s;
    __syncthreads();
    s = red2[0];
#pragma unroll
    for (int i = 1; i < 8; i++) s += red2[i];

    const float inv = 1.0f / s;
#pragma unroll
    for (int i = 0; i < 4; i++) {
        r[i].x *= inv; r[i].y *= inv; r[i].z *= inv; r[i].w *= inv;
        p4[tid + 256 * i] = r[i];
    }
}

// ---------------------------------------------------------------------------
extern "C" void kernel_launch(void* const* d_in, const int* in_sizes, int n_in,
                              void* d_out, int out_size)
{
    const float* query = (const float*)d_in[0];
    const float* key   = (const float*)d_in[1];
    const float* value = (const float*)d_in[2];
    const float* Wq    = (const float*)d_in[3];
    const float* bq    = (const float*)d_in[4];
    const float* Wk    = (const float*)d_in[5];
    const float* bk    = (const float*)d_in[6];
    const float* Wv    = (const float*)d_in[7];
    const float* bv    = (const float*)d_in[8];
    float* out = (float*)d_out;

    float *q, *k, *v, *sc;
    cudaGetSymbolAddress((void**)&q,  g_q);
    cudaGetSymbolAddress((void**)&k,  g_k);
    cudaGetSymbolAddress((void**)&v,  g_v);
    cudaGetSymbolAddress((void**)&sc, g_scores);

    const int M_proj = BB * SS;                 // 16384
    const long long strideQ = (long long)SS * EE;    // 2,097,152
    const long long strideS = (long long)SS * SS;    // 16,777,216

    // 1) Projections: X[16384,512] @ W^T[512,512] + b
    {
        dim3 grid(EE / 128, M_proj / 128, 1);
        sgemm_kernel<true, true><<<grid, 256>>>(query, Wq, bq, q, M_proj, EE, EE, 0, 0, 0);
        sgemm_kernel<true, true><<<grid, 256>>>(key,   Wk, bk, k, M_proj, EE, EE, 0, 0, 0);
        sgemm_kernel<true, true><<<grid, 256>>>(value, Wv, bv, v, M_proj, EE, EE, 0, 0, 0);
    }

    // 2) scores[b] = Q_b[4096,512] @ K_b^T
    {
        dim3 grid(SS / 128, SS / 128, BB);
        sgemm_kernel<true, false><<<grid, 256>>>(q, k, nullptr, sc,
                                                 SS, SS, EE, strideQ, strideQ, strideS);
    }

    // 3) softmax over rows
    softmax_kernel<<<BB * SS, 256>>>(sc);

    // 4) out[b] = attn_b[4096,4096] @ V_b[4096,512]
    {
        dim3 grid(EE / 128, SS / 128, BB);
        sgemm_kernel<false, false><<<grid, 256>>>(sc, v, nullptr, out,
                                                  SS, EE, SS, strideS, strideQ, strideQ);
    }
}

// round 4
// speedup vs baseline: 3.3649x; 3.3649x over previous
#include <cuda_runtime.h>
#include <cuda_bf16.h>
#include <cstdint>
#include <math.h>

#define BB 4
#define SS 4096
#define EE 512

// ---------------------------------------------------------------------------
// Scratch (__device__ globals; allocation-free rule)
// ---------------------------------------------------------------------------
__device__ __nv_bfloat16 g_xq_hi[(size_t)BB*SS*EE], g_xq_lo[(size_t)BB*SS*EE];
__device__ __nv_bfloat16 g_xk_hi[(size_t)BB*SS*EE], g_xk_lo[(size_t)BB*SS*EE];
__device__ __nv_bfloat16 g_xv_hi[(size_t)BB*SS*EE], g_xv_lo[(size_t)BB*SS*EE];
__device__ __nv_bfloat16 g_wq_hi[(size_t)EE*EE],    g_wq_lo[(size_t)EE*EE];
__device__ __nv_bfloat16 g_wk_hi[(size_t)EE*EE],    g_wk_lo[(size_t)EE*EE];
__device__ __nv_bfloat16 g_wv_hi[(size_t)EE*EE],    g_wv_lo[(size_t)EE*EE];
__device__ __nv_bfloat16 g_q_hi[(size_t)BB*SS*EE],  g_q_lo[(size_t)BB*SS*EE];
__device__ __nv_bfloat16 g_k_hi[(size_t)BB*SS*EE],  g_k_lo[(size_t)BB*SS*EE];
__device__ __nv_bfloat16 g_vt_hi[(size_t)BB*EE*SS], g_vt_lo[(size_t)BB*EE*SS];
__device__ float         g_scores[(size_t)BB*SS*SS];
__device__ __nv_bfloat16 g_attn_hi[(size_t)BB*SS*SS], g_attn_lo[(size_t)BB*SS*SS];

// ---------------------------------------------------------------------------
// Helpers
// ---------------------------------------------------------------------------
__device__ __forceinline__ uint32_t smem_u32(const void* p) {
    uint32_t a;
    asm("{ .reg .u64 t; cvta.to.shared.u64 t, %1; cvt.u32.u64 %0, t; }"
        : "=r"(a) : "l"(p));
    return a;
}

#define CP_ASYNC16(sm, g) \
    asm volatile("cp.async.cg.shared.global [%0], [%1], 16;" :: "r"(sm), "l"(g))
#define CP_COMMIT() asm volatile("cp.async.commit_group;" ::: "memory")
#define CP_WAIT(n)  asm volatile("cp.async.wait_group %0;" :: "n"(n) : "memory")

__device__ __forceinline__ void ldsm_x4(uint32_t* r, uint32_t addr) {
    asm volatile("ldmatrix.sync.aligned.m8n8.x4.shared.b16 {%0,%1,%2,%3}, [%4];"
        : "=r"(r[0]), "=r"(r[1]), "=r"(r[2]), "=r"(r[3]) : "r"(addr));
}

__device__ __forceinline__ void mma_bf16(float* d, const uint32_t* a, const uint32_t* b) {
    asm volatile(
        "mma.sync.aligned.m16n8k16.row.col.f32.bf16.bf16.f32 "
        "{%0,%1,%2,%3}, {%4,%5,%6,%7}, {%8,%9}, {%0,%1,%2,%3};"
        : "+f"(d[0]), "+f"(d[1]), "+f"(d[2]), "+f"(d[3])
        : "r"(a[0]), "r"(a[1]), "r"(a[2]), "r"(a[3]), "r"(b[0]), "r"(b[1]));
}

// swizzled smem byte offset for a [rows][32 bf16] tile (64B rows):
// 16B unit u in row r goes to u ^ ((r>>1)&3)  -> conflict-free ldmatrix
__device__ __forceinline__ uint32_t sw_off(int r, int u) {
    return (uint32_t)(r * 64 + ((u ^ ((r >> 1) & 3)) << 4));
}

__device__ __forceinline__ uint32_t pk2(__nv_bfloat16 a, __nv_bfloat16 b) {
    __nv_bfloat162 t = __halves2bfloat162(a, b);
    return *reinterpret_cast<uint32_t*>(&t);
}

// ---------------------------------------------------------------------------
// HMMA split-bf16 GEMM: C[M,N] = A[M,K] @ B[N,K]^T (+bias), batched (z).
// A,B given as hi/lo bf16 pairs (K-major). Uses hi*hi + hi*lo + lo*hi.
// Block tile 128x128, BK=32, 8 warps (4m x 2n), warp tile 32x64.
// 3-stage cp.async pipeline, 32KB/stage.
// OUT_SPLIT: write bf16 hi/lo instead of fp32. BIAS_MODE: 0 none, 1 per-N, 2 per-M.
// ---------------------------------------------------------------------------
constexpr int NS = 3;
constexpr int STG = 32768;                 // Ahi8K + Alo8K + Bhi8K + Blo8K
constexpr int GEMM_SMEM = NS * STG;        // 98304

template <bool OUT_SPLIT, int BIAS_MODE>
__global__ __launch_bounds__(256) void mma_gemm(
    const __nv_bfloat16* __restrict__ Ahi, const __nv_bfloat16* __restrict__ Alo,
    const __nv_bfloat16* __restrict__ Bhi, const __nv_bfloat16* __restrict__ Blo,
    const float* __restrict__ bias,
    float* __restrict__ Cf, __nv_bfloat16* __restrict__ Chi, __nv_bfloat16* __restrict__ Clo,
    int M, int N, int K,
    long long sA, long long sB, long long sC)
{
    extern __shared__ __align__(1024) char smem[];
    const uint32_t sbase = smem_u32(smem);

    const int tid = threadIdx.x;
    const int lane = tid & 31;
    const int wid = tid >> 5;
    const int warp_m = wid & 3;      // 0..3 -> 32-row slab
    const int warp_n = wid >> 2;     // 0..1 -> 64-col slab

    const long long bz = blockIdx.z;
    Ahi += bz * sA;  Alo += bz * sA;
    Bhi += bz * sB;  Blo += bz * sB;

    const int row0 = blockIdx.y * 128;
    const int col0 = blockIdx.x * 128;

    float acc[2][8][4];
#pragma unroll
    for (int a = 0; a < 2; a++)
#pragma unroll
        for (int b = 0; b < 8; b++)
#pragma unroll
            for (int c = 0; c < 4; c++) acc[a][b][c] = 0.0f;

    // loader: chunk c (32 k-cols) into stage st. Each tile 128x32 bf16 = 512x16B.
    auto issue_stage = [&](int c, int st) {
        const long long k0 = (long long)c * 32;
        const uint32_t s0 = sbase + st * STG;
#pragma unroll
        for (int i = 0; i < 2; i++) {
            const int f = tid + i * 256;
            const int r = f >> 2, u = f & 3;
            const uint32_t so = sw_off(r, u);
            const long long ga = (long long)(row0 + r) * K + k0 + u * 8;
            const long long gb = (long long)(col0 + r) * K + k0 + u * 8;
            CP_ASYNC16(s0 + so,         (const void*)(Ahi + ga));
            CP_ASYNC16(s0 + 8192 + so,  (const void*)(Alo + ga));
            CP_ASYNC16(s0 + 16384 + so, (const void*)(Bhi + gb));
            CP_ASYNC16(s0 + 24576 + so, (const void*)(Blo + gb));
        }
    };

    const int nch = K / 32;
    issue_stage(0, 0); CP_COMMIT();
    issue_stage(1, 1); CP_COMMIT();

    for (int c = 0; c < nch; c++) {
        CP_WAIT(1);
        __syncthreads();
        if (c + 2 < nch) issue_stage(c + 2, (c + 2) % NS);
        CP_COMMIT();

        const uint32_t s0 = sbase + (c % NS) * STG;
#pragma unroll
        for (int ks = 0; ks < 2; ks++) {
            uint32_t ah[2][4], al[2][4], bh[16], bl[16];
#pragma unroll
            for (int mt = 0; mt < 2; mt++) {
                const int r = warp_m * 32 + mt * 16 + (lane & 15);
                const int u = ks * 2 + (lane >> 4);
                const uint32_t ad = s0 + sw_off(r, u);
                ldsm_x4(ah[mt], ad);
                ldsm_x4(al[mt], ad + 8192);
            }
#pragma unroll
            for (int g = 0; g < 4; g++) {
                const int r = warp_n * 64 + g * 16 + (lane & 7) + ((lane >> 4) & 1) * 8;
                const int u = ks * 2 + ((lane >> 3) & 1);
                const uint32_t bd = s0 + 16384 + sw_off(r, u);
                ldsm_x4(&bh[g * 4], bd);
                ldsm_x4(&bl[g * 4], bd + 8192);
            }
#pragma unroll
            for (int mt = 0; mt < 2; mt++)
#pragma unroll
                for (int j = 0; j < 8; j++) {
                    mma_bf16(acc[mt][j], ah[mt], &bh[2 * j]);   // hi*hi
                    mma_bf16(acc[mt][j], ah[mt], &bl[2 * j]);   // hi*lo
                    mma_bf16(acc[mt][j], al[mt], &bh[2 * j]);   // lo*hi
                }
        }
    }

    // ---- epilogue ----
    const long long cb = bz * sC;
#pragma unroll
    for (int mt = 0; mt < 2; mt++) {
        const int rb = row0 + warp_m * 32 + mt * 16 + (lane >> 2);
#pragma unroll
        for (int half = 0; half < 2; half++) {
            const long long row = rb + half * 8;
            float bm = 0.0f;
            if (BIAS_MODE == 2) bm = bias[row];
#pragma unroll
            for (int j = 0; j < 8; j++) {
                const int col = col0 + warp_n * 64 + j * 8 + (lane & 3) * 2;
                float v0 = acc[mt][j][half * 2 + 0] + bm;
                float v1 = acc[mt][j][half * 2 + 1] + bm;
                if (BIAS_MODE == 1) { v0 += bias[col]; v1 += bias[col + 1]; }
                if (OUT_SPLIT) {
                    const __nv_bfloat16 h0 = __float2bfloat16(v0);
                    const __nv_bfloat16 h1 = __float2bfloat16(v1);
                    const __nv_bfloat16 l0 = __float2bfloat16(v0 - __bfloat162float(h0));
                    const __nv_bfloat16 l1 = __float2bfloat16(v1 - __bfloat162float(h1));
                    *(uint32_t*)(Chi + cb + row * (long long)N + col) = pk2(h0, h1);
                    *(uint32_t*)(Clo + cb + row * (long long)N + col) = pk2(l0, l1);
                } else {
                    float2 vv; vv.x = v0; vv.y = v1;
                    *(float2*)(Cf + cb + row * (long long)N + col) = vv;
                }
            }
        }
    }
}

// ---------------------------------------------------------------------------
// fp32 -> bf16 hi/lo split (elementwise, float4 granularity)
// ---------------------------------------------------------------------------
__global__ __launch_bounds__(256) void split_kernel(
    const float4* __restrict__ in, uint2* __restrict__ hi, uint2* __restrict__ lo, int n4)
{
    const int i = blockIdx.x * 256 + threadIdx.x;
    if (i >= n4) return;
    const float4 v = in[i];
    const __nv_bfloat16 h0 = __float2bfloat16(v.x), h1 = __float2bfloat16(v.y);
    const __nv_bfloat16 h2 = __float2bfloat16(v.z), h3 = __float2bfloat16(v.w);
    const __nv_bfloat16 l0 = __float2bfloat16(v.x - __bfloat162float(h0));
    const __nv_bfloat16 l1 = __float2bfloat16(v.y - __bfloat162float(h1));
    const __nv_bfloat16 l2 = __float2bfloat16(v.z - __bfloat162float(h2));
    const __nv_bfloat16 l3 = __float2bfloat16(v.w - __bfloat162float(h3));
    uint2 H, L;
    H.x = pk2(h0, h1); H.y = pk2(h2, h3);
    L.x = pk2(l0, l1); L.y = pk2(l2, l3);
    hi[i] = H;  lo[i] = L;
}

// ---------------------------------------------------------------------------
// Softmax over rows of 4096 fp32 scores -> bf16 hi/lo attn (fused split)
// ---------------------------------------------------------------------------
__global__ __launch_bounds__(256) void softmax_split_kernel(
    const float* __restrict__ scores,
    __nv_bfloat16* __restrict__ ahi, __nv_bfloat16* __restrict__ alo)
{
    const long long row = blockIdx.x;
    const float4* p4 = (const float4*)(scores + row * (long long)SS);
    uint2* h2 = (uint2*)(ahi + row * (long long)SS);
    uint2* l2 = (uint2*)(alo + row * (long long)SS);
    const int tid = threadIdx.x;
    const int lane = tid & 31;
    const int wid = tid >> 5;

    float4 r[4];
    float m = -1e30f;
#pragma unroll
    for (int i = 0; i < 4; i++) {
        r[i] = p4[tid + 256 * i];
        m = fmaxf(m, fmaxf(fmaxf(r[i].x, r[i].y), fmaxf(r[i].z, r[i].w)));
    }
#pragma unroll
    for (int o = 16; o > 0; o >>= 1) m = fmaxf(m, __shfl_xor_sync(0xffffffffu, m, o));
    __shared__ float red[8];
    if (lane == 0) red[wid] = m;
    __syncthreads();
    m = red[0];
#pragma unroll
    for (int i = 1; i < 8; i++) m = fmaxf(m, red[i]);

    float s = 0.0f;
#pragma unroll
    for (int i = 0; i < 4; i++) {
        r[i].x = __expf(r[i].x - m);  r[i].y = __expf(r[i].y - m);
        r[i].z = __expf(r[i].z - m);  r[i].w = __expf(r[i].w - m);
        s += r[i].x + r[i].y + r[i].z + r[i].w;
    }
#pragma unroll
    for (int o = 16; o > 0; o >>= 1) s += __shfl_xor_sync(0xffffffffu, s, o);
    __shared__ float red2[8];
    if (lane == 0) red2[wid] = s;
    __syncthreads();
    s = red2[0];
#pragma unroll
    for (int i = 1; i < 8; i++) s += red2[i];

    const float inv = 1.0f / s;
#pragma unroll
    for (int i = 0; i < 4; i++) {
        const float v0 = r[i].x * inv, v1 = r[i].y * inv;
        const float v2 = r[i].z * inv, v3 = r[i].w * inv;
        const __nv_bfloat16 h0 = __float2bfloat16(v0), h1 = __float2bfloat16(v1);
        const __nv_bfloat16 h2b = __float2bfloat16(v2), h3 = __float2bfloat16(v3);
        const __nv_bfloat16 l0 = __float2bfloat16(v0 - __bfloat162float(h0));
        const __nv_bfloat16 l1 = __float2bfloat16(v1 - __bfloat162float(h1));
        const __nv_bfloat16 l2v = __float2bfloat16(v2 - __bfloat162float(h2b));
        const __nv_bfloat16 l3 = __float2bfloat16(v3 - __bfloat162float(h3));
        uint2 H, L;
        H.x = pk2(h0, h1); H.y = pk2(h2b, h3);
        L.x = pk2(l0, l1); L.y = pk2(l2v, l3);
        h2[tid + 256 * i] = H;
        l2[tid + 256 * i] = L;
    }
}

// ---------------------------------------------------------------------------
extern "C" void kernel_launch(void* const* d_in, const int* in_sizes, int n_in,
                              void* d_out, int out_size)
{
    const float* query = (const float*)d_in[0];
    const float* key   = (const float*)d_in[1];
    const float* value = (const float*)d_in[2];
    const float* Wq    = (const float*)d_in[3];
    const float* bq    = (const float*)d_in[4];
    const float* Wk    = (const float*)d_in[5];
    const float* bk    = (const float*)d_in[6];
    const float* Wv    = (const float*)d_in[7];
    const float* bv    = (const float*)d_in[8];
    float* out = (float*)d_out;

    __nv_bfloat16 *xq_hi, *xq_lo, *xk_hi, *xk_lo, *xv_hi, *xv_lo;
    __nv_bfloat16 *wq_hi, *wq_lo, *wk_hi, *wk_lo, *wv_hi, *wv_lo;
    __nv_bfloat16 *q_hi, *q_lo, *k_hi, *k_lo, *vt_hi, *vt_lo, *a_hi, *a_lo;
    float* sc;
    cudaGetSymbolAddress((void**)&xq_hi, g_xq_hi); cudaGetSymbolAddress((void**)&xq_lo, g_xq_lo);
    cudaGetSymbolAddress((void**)&xk_hi, g_xk_hi); cudaGetSymbolAddress((void**)&xk_lo, g_xk_lo);
    cudaGetSymbolAddress((void**)&xv_hi, g_xv_hi); cudaGetSymbolAddress((void**)&xv_lo, g_xv_lo);
    cudaGetSymbolAddress((void**)&wq_hi, g_wq_hi); cudaGetSymbolAddress((void**)&wq_lo, g_wq_lo);
    cudaGetSymbolAddress((void**)&wk_hi, g_wk_hi); cudaGetSymbolAddress((void**)&wk_lo, g_wk_lo);
    cudaGetSymbolAddress((void**)&wv_hi, g_wv_hi); cudaGetSymbolAddress((void**)&wv_lo, g_wv_lo);
    cudaGetSymbolAddress((void**)&q_hi,  g_q_hi);  cudaGetSymbolAddress((void**)&q_lo,  g_q_lo);
    cudaGetSymbolAddress((void**)&k_hi,  g_k_hi);  cudaGetSymbolAddress((void**)&k_lo,  g_k_lo);
    cudaGetSymbolAddress((void**)&vt_hi, g_vt_hi); cudaGetSymbolAddress((void**)&vt_lo, g_vt_lo);
    cudaGetSymbolAddress((void**)&a_hi,  g_attn_hi); cudaGetSymbolAddress((void**)&a_lo, g_attn_lo);
    cudaGetSymbolAddress((void**)&sc,    g_scores);

    cudaFuncSetAttribute(mma_gemm<false, 0>, cudaFuncAttributeMaxDynamicSharedMemorySize, GEMM_SMEM);
    cudaFuncSetAttribute(mma_gemm<true, 1>,  cudaFuncAttributeMaxDynamicSharedMemorySize, GEMM_SMEM);
    cudaFuncSetAttribute(mma_gemm<true, 2>,  cudaFuncAttributeMaxDynamicSharedMemorySize, GEMM_SMEM);

    const long long nIn  = (long long)BB * SS * EE;   // 8388608
    const long long nW   = (long long)EE * EE;        // 262144
    const long long strideQ = (long long)SS * EE;
    const long long strideS = (long long)SS * SS;

    // 1) split inputs + weights to bf16 hi/lo
    split_kernel<<<(int)(nIn / 4 / 256), 256>>>((const float4*)query, (uint2*)xq_hi, (uint2*)xq_lo, (int)(nIn / 4));
    split_kernel<<<(int)(nIn / 4 / 256), 256>>>((const float4*)key,   (uint2*)xk_hi, (uint2*)xk_lo, (int)(nIn / 4));
    split_kernel<<<(int)(nIn / 4 / 256), 256>>>((const float4*)value, (uint2*)xv_hi, (uint2*)xv_lo, (int)(nIn / 4));
    split_kernel<<<(int)(nW / 4 / 256), 256>>>((const float4*)Wq, (uint2*)wq_hi, (uint2*)wq_lo, (int)(nW / 4));
    split_kernel<<<(int)(nW / 4 / 256), 256>>>((const float4*)Wk, (uint2*)wk_hi, (uint2*)wk_lo, (int)(nW / 4));
    split_kernel<<<(int)(nW / 4 / 256), 256>>>((const float4*)Wv, (uint2*)wv_hi, (uint2*)wv_lo, (int)(nW / 4));

    // 2) q/k projections: [16384,512] = x @ W^T + b (split-bf16 output)
    {
        dim3 g(EE / 128, (BB * SS) / 128, 1);
        mma_gemm<true, 1><<<g, 256, GEMM_SMEM>>>(xq_hi, xq_lo, wq_hi, wq_lo, bq,
                                                 nullptr, q_hi, q_lo,
                                                 BB * SS, EE, EE, 0, 0, 0);
        mma_gemm<true, 1><<<g, 256, GEMM_SMEM>>>(xk_hi, xk_lo, wk_hi, wk_lo, bk,
                                                 nullptr, k_hi, k_lo,
                                                 BB * SS, EE, EE, 0, 0, 0);
    }

    // 3) v projection, transposed: vT[b] [E,S] = Wv @ value[b]^T + bv (per-row bias)
    {
        dim3 g(SS / 128, EE / 128, BB);
        mma_gemm<true, 2><<<g, 256, GEMM_SMEM>>>(wv_hi, wv_lo, xv_hi, xv_lo, bv,
                                                 nullptr, vt_hi, vt_lo,
                                                 EE, SS, EE, 0, strideQ, (long long)EE * SS);
    }

    // 4) scores[b] = q[b] @ k[b]^T (fp32 out)
    {
        dim3 g(SS / 128, SS / 128, BB);
        mma_gemm<false, 0><<<g, 256, GEMM_SMEM>>>(q_hi, q_lo, k_hi, k_lo, nullptr,
                                                  sc, nullptr, nullptr,
                                                  SS, SS, EE, strideQ, strideQ, strideS);
    }

    // 5) softmax + fused attn split
    softmax_split_kernel<<<BB * SS, 256>>>(sc, a_hi, a_lo);

    // 6) out[b] = attn[b] @ vT[b]^T (fp32 out)
    {
        dim3 g(EE / 128, SS / 128, BB);
        mma_gemm<false, 0><<<g, 256, GEMM_SMEM>>>(a_hi, a_lo, vt_hi, vt_lo, nullptr,
                                                  out, nullptr, nullptr,
                                                  SS, EE, SS, strideS, (long long)EE * SS, strideQ);
    }
}

// round 5
// speedup vs baseline: 4.7077x; 1.3991x over previous
#include <cuda_runtime.h>
#include <cuda_fp16.h>
#include <cstdint>
#include <math.h>

#define BB 4
#define SS 4096
#define EE 512

// ---------------------------------------------------------------------------
// Scratch (__device__ globals; allocation-free rule)
// ---------------------------------------------------------------------------
__device__ __half g_xq_hi[(size_t)BB*SS*EE], g_xq_lo[(size_t)BB*SS*EE];
__device__ __half g_xk_hi[(size_t)BB*SS*EE], g_xk_lo[(size_t)BB*SS*EE];
__device__ __half g_xv_hi[(size_t)BB*SS*EE];
__device__ __half g_wq_hi[(size_t)EE*EE],    g_wq_lo[(size_t)EE*EE];
__device__ __half g_wk_hi[(size_t)EE*EE],    g_wk_lo[(size_t)EE*EE];
__device__ __half g_wv_hi[(size_t)EE*EE],    g_wv_lo[(size_t)EE*EE];
__device__ __half g_q_hi[(size_t)BB*SS*EE],  g_q_lo[(size_t)BB*SS*EE];
__device__ __half g_k_hi[(size_t)BB*SS*EE],  g_k_lo[(size_t)BB*SS*EE];
__device__ __half g_vt[(size_t)BB*EE*SS];
__device__ float  g_scores[(size_t)BB*SS*SS];
__device__ __half g_attn[(size_t)BB*SS*SS];

// ---------------------------------------------------------------------------
// Helpers
// ---------------------------------------------------------------------------
__device__ __forceinline__ uint32_t smem_u32(const void* p) {
    uint32_t a;
    asm("{ .reg .u64 t; cvta.to.shared.u64 t, %1; cvt.u32.u64 %0, t; }"
        : "=r"(a) : "l"(p));
    return a;
}

#define CP_ASYNC16(sm, g) \
    asm volatile("cp.async.cg.shared.global [%0], [%1], 16;" :: "r"(sm), "l"(g))
#define CP_COMMIT() asm volatile("cp.async.commit_group;" ::: "memory")
#define CP_WAIT(n)  asm volatile("cp.async.wait_group %0;" :: "n"(n) : "memory")

__device__ __forceinline__ void ldsm_x4(uint32_t* r, uint32_t addr) {
    asm volatile("ldmatrix.sync.aligned.m8n8.x4.shared.b16 {%0,%1,%2,%3}, [%4];"
        : "=r"(r[0]), "=r"(r[1]), "=r"(r[2]), "=r"(r[3]) : "r"(addr));
}

__device__ __forceinline__ void mma_f16(float* d, const uint32_t* a, const uint32_t* b) {
    asm volatile(
        "mma.sync.aligned.m16n8k16.row.col.f32.f16.f16.f32 "
        "{%0,%1,%2,%3}, {%4,%5,%6,%7}, {%8,%9}, {%0,%1,%2,%3};"
        : "+f"(d[0]), "+f"(d[1]), "+f"(d[2]), "+f"(d[3])
        : "r"(a[0]), "r"(a[1]), "r"(a[2]), "r"(a[3]), "r"(b[0]), "r"(b[1]));
}

// swizzled smem byte offset for a [rows][32 f16] tile (64B rows)
__device__ __forceinline__ uint32_t sw_off(int r, int u) {
    return (uint32_t)(r * 64 + ((u ^ ((r >> 1) & 3)) << 4));
}

__device__ __forceinline__ uint32_t pk2h(__half a, __half b) {
    __half2 t = __halves2half2(a, b);
    return *reinterpret_cast<uint32_t*>(&t);
}

// ---------------------------------------------------------------------------
// HMMA split-fp16 GEMM: C[M,N] = A[M,K] @ B[N,K]^T (+bias), batched (z).
// TERMS: 3 = Ah*Bh + Ah*Bl + Al*Bh, 2 = Ah*Bh + Al*Bh, 1 = Ah*Bh.
// OUT_MODE: 0 fp32, 1 fp16 hi/lo split, 2 fp16 single.
// BIAS_MODE: 0 none, 1 per-N, 2 per-M.
// Block tile 128x128, BK=32, 8 warps (4m x 2n), 3-stage cp.async pipeline.
// ---------------------------------------------------------------------------
constexpr int NS = 3;
template <int TERMS> struct StgB { static constexpr int v = 8192 * (TERMS == 3 ? 4 : TERMS == 2 ? 3 : 2); };

template <int TERMS, int OUT_MODE, int BIAS_MODE>
__global__ __launch_bounds__(256) void mma_gemm(
    const __half* __restrict__ Ahi, const __half* __restrict__ Alo,
    const __half* __restrict__ Bhi, const __half* __restrict__ Blo,
    const float* __restrict__ bias,
    float* __restrict__ Cf, __half* __restrict__ Ch, __half* __restrict__ Cl,
    int M, int N, int K,
    long long sA, long long sB, long long sC)
{
    constexpr int STG   = StgB<TERMS>::v;
    constexpr int offAl = 8192;
    constexpr int offBh = (TERMS >= 2) ? 16384 : 8192;
    constexpr int offBl = offBh + 8192;

    extern __shared__ __align__(1024) char smem[];
    const uint32_t sbase = smem_u32(smem);

    const int tid = threadIdx.x;
    const int lane = tid & 31;
    const int wid = tid >> 5;
    const int warp_m = wid & 3;
    const int warp_n = wid >> 2;

    const long long bz = blockIdx.z;
    Ahi += bz * sA;  if (TERMS >= 2) Alo += bz * sA;
    Bhi += bz * sB;  if (TERMS == 3) Blo += bz * sB;

    const int row0 = blockIdx.y * 128;
    const int col0 = blockIdx.x * 128;

    float acc[2][8][4];
#pragma unroll
    for (int a = 0; a < 2; a++)
#pragma unroll
        for (int b = 0; b < 8; b++)
#pragma unroll
            for (int c = 0; c < 4; c++) acc[a][b][c] = 0.0f;

    auto issue_stage = [&](int c, int st) {
        const long long k0 = (long long)c * 32;
        const uint32_t s0 = sbase + st * STG;
#pragma unroll
        for (int i = 0; i < 2; i++) {
            const int f = tid + i * 256;
            const int r = f >> 2, u = f & 3;
            const uint32_t so = sw_off(r, u);
            const long long ga = (long long)(row0 + r) * K + k0 + u * 8;
            const long long gb = (long long)(col0 + r) * K + k0 + u * 8;
            CP_ASYNC16(s0 + so, (const void*)(Ahi + ga));
            if (TERMS >= 2) CP_ASYNC16(s0 + offAl + so, (const void*)(Alo + ga));
            CP_ASYNC16(s0 + offBh + so, (const void*)(Bhi + gb));
            if (TERMS == 3) CP_ASYNC16(s0 + offBl + so, (const void*)(Blo + gb));
        }
    };

    const int nch = K / 32;
    issue_stage(0, 0); CP_COMMIT();
    issue_stage(1, 1); CP_COMMIT();

    for (int c = 0; c < nch; c++) {
        CP_WAIT(1);
        __syncthreads();
        if (c + 2 < nch) issue_stage(c + 2, (c + 2) % NS);
        CP_COMMIT();

        const uint32_t s0 = sbase + (c % NS) * STG;
#pragma unroll
        for (int ks = 0; ks < 2; ks++) {
            uint32_t ah[2][4], al[2][4], bh[16], bl[16];
#pragma unroll
            for (int mt = 0; mt < 2; mt++) {
                const int r = warp_m * 32 + mt * 16 + (lane & 15);
                const int u = ks * 2 + (lane >> 4);
                const uint32_t ad = s0 + sw_off(r, u);
                ldsm_x4(ah[mt], ad);
                if (TERMS >= 2) ldsm_x4(al[mt], ad + offAl);
            }
#pragma unroll
            for (int g = 0; g < 4; g++) {
                const int r = warp_n * 64 + g * 16 + (lane & 7) + ((lane >> 4) & 1) * 8;
                const int u = ks * 2 + ((lane >> 3) & 1);
                const uint32_t bd = s0 + offBh + sw_off(r, u);
                ldsm_x4(&bh[g * 4], bd);
                if (TERMS == 3) ldsm_x4(&bl[g * 4], bd + 8192);
            }
#pragma unroll
            for (int mt = 0; mt < 2; mt++)
#pragma unroll
                for (int j = 0; j < 8; j++) {
                    mma_f16(acc[mt][j], ah[mt], &bh[2 * j]);
                    if (TERMS == 3) mma_f16(acc[mt][j], ah[mt], &bl[2 * j]);
                    if (TERMS >= 2) mma_f16(acc[mt][j], al[mt], &bh[2 * j]);
                }
        }
    }

    // ---- epilogue ----
    const long long cb = bz * sC;
#pragma unroll
    for (int mt = 0; mt < 2; mt++) {
        const int rb = row0 + warp_m * 32 + mt * 16 + (lane >> 2);
#pragma unroll
        for (int half = 0; half < 2; half++) {
            const long long row = rb + half * 8;
            float bm = 0.0f;
            if (BIAS_MODE == 2) bm = bias[row];
#pragma unroll
            for (int j = 0; j < 8; j++) {
                const int col = col0 + warp_n * 64 + j * 8 + (lane & 3) * 2;
                float v0 = acc[mt][j][half * 2 + 0] + bm;
                float v1 = acc[mt][j][half * 2 + 1] + bm;
                if (BIAS_MODE == 1) { v0 += bias[col]; v1 += bias[col + 1]; }
                if (OUT_MODE == 1) {
                    const __half h0 = __float2half_rn(v0);
                    const __half h1 = __float2half_rn(v1);
                    const __half l0 = __float2half_rn(v0 - __half2float(h0));
                    const __half l1 = __float2half_rn(v1 - __half2float(h1));
                    *(uint32_t*)(Ch + cb + row * (long long)N + col) = pk2h(h0, h1);
                    *(uint32_t*)(Cl + cb + row * (long long)N + col) = pk2h(l0, l1);
                } else if (OUT_MODE == 2) {
                    *(uint32_t*)(Ch + cb + row * (long long)N + col) =
                        pk2h(__float2half_rn(v0), __float2half_rn(v1));
                } else {
                    float2 vv; vv.x = v0; vv.y = v1;
                    *(float2*)(Cf + cb + row * (long long)N + col) = vv;
                }
            }
        }
    }
}

// ---------------------------------------------------------------------------
// fp32 -> fp16 hi/lo split
// ---------------------------------------------------------------------------
__global__ __launch_bounds__(256) void split2_kernel(
    const float4* __restrict__ in, uint2* __restrict__ hi, uint2* __restrict__ lo, int n4)
{
    const int i = blockIdx.x * 256 + threadIdx.x;
    if (i >= n4) return;
    const float4 v = in[i];
    const __half h0 = __float2half_rn(v.x), h1 = __float2half_rn(v.y);
    const __half h2 = __float2half_rn(v.z), h3 = __float2half_rn(v.w);
    const __half l0 = __float2half_rn(v.x - __half2float(h0));
    const __half l1 = __float2half_rn(v.y - __half2float(h1));
    const __half l2 = __float2half_rn(v.z - __half2float(h2));
    const __half l3 = __float2half_rn(v.w - __half2float(h3));
    uint2 H, L;
    H.x = pk2h(h0, h1); H.y = pk2h(h2, h3);
    L.x = pk2h(l0, l1); L.y = pk2h(l2, l3);
    hi[i] = H;  lo[i] = L;
}

// fp32 -> fp16 single
__global__ __launch_bounds__(256) void cvt1_kernel(
    const float4* __restrict__ in, uint2* __restrict__ hi, int n4)
{
    const int i = blockIdx.x * 256 + threadIdx.x;
    if (i >= n4) return;
    const float4 v = in[i];
    uint2 H;
    H.x = pk2h(__float2half_rn(v.x), __float2half_rn(v.y));
    H.y = pk2h(__float2half_rn(v.z), __float2half_rn(v.w));
    hi[i] = H;
}

// ---------------------------------------------------------------------------
// Softmax over rows of 4096 fp32 scores -> fp16 attn
// ---------------------------------------------------------------------------
__global__ __launch_bounds__(256) void softmax_kernel(
    const float* __restrict__ scores, __half* __restrict__ attn)
{
    const long long row = blockIdx.x;
    const float4* p4 = (const float4*)(scores + row * (long long)SS);
    uint2* h2 = (uint2*)(attn + row * (long long)SS);
    const int tid = threadIdx.x;
    const int lane = tid & 31;
    const int wid = tid >> 5;

    float4 r[4];
    float m = -1e30f;
#pragma unroll
    for (int i = 0; i < 4; i++) {
        r[i] = p4[tid + 256 * i];
        m = fmaxf(m, fmaxf(fmaxf(r[i].x, r[i].y), fmaxf(r[i].z, r[i].w)));
    }
#pragma unroll
    for (int o = 16; o > 0; o >>= 1) m = fmaxf(m, __shfl_xor_sync(0xffffffffu, m, o));
    __shared__ float red[8];
    if (lane == 0) red[wid] = m;
    __syncthreads();
    m = red[0];
#pragma unroll
    for (int i = 1; i < 8; i++) m = fmaxf(m, red[i]);

    float s = 0.0f;
#pragma unroll
    for (int i = 0; i < 4; i++) {
        r[i].x = __expf(r[i].x - m);  r[i].y = __expf(r[i].y - m);
        r[i].z = __expf(r[i].z - m);  r[i].w = __expf(r[i].w - m);
        s += r[i].x + r[i].y + r[i].z + r[i].w;
    }
#pragma unroll
    for (int o = 16; o > 0; o >>= 1) s += __shfl_xor_sync(0xffffffffu, s, o);
    __shared__ float red2[8];
    if (lane == 0) red2[wid] = s;
    __syncthreads();
    s = red2[0];
#pragma unroll
    for (int i = 1; i < 8; i++) s += red2[i];

    const float inv = 1.0f / s;
#pragma unroll
    for (int i = 0; i < 4; i++) {
        uint2 H;
        H.x = pk2h(__float2half_rn(r[i].x * inv), __float2half_rn(r[i].y * inv));
        H.y = pk2h(__float2half_rn(r[i].z * inv), __float2half_rn(r[i].w * inv));
        h2[tid + 256 * i] = H;
    }
}

// ---------------------------------------------------------------------------
extern "C" void kernel_launch(void* const* d_in, const int* in_sizes, int n_in,
                              void* d_out, int out_size)
{
    const float* query = (const float*)d_in[0];
    const float* key   = (const float*)d_in[1];
    const float* value = (const float*)d_in[2];
    const float* Wq    = (const float*)d_in[3];
    const float* bq    = (const float*)d_in[4];
    const float* Wk    = (const float*)d_in[5];
    const float* bk    = (const float*)d_in[6];
    const float* Wv    = (const float*)d_in[7];
    const float* bv    = (const float*)d_in[8];
    float* out = (float*)d_out;

    __half *xq_hi, *xq_lo, *xk_hi, *xk_lo, *xv_hi;
    __half *wq_hi, *wq_lo, *wk_hi, *wk_lo, *wv_hi, *wv_lo;
    __half *q_hi, *q_lo, *k_hi, *k_lo, *vt, *attn;
    float* sc;
    cudaGetSymbolAddress((void**)&xq_hi, g_xq_hi); cudaGetSymbolAddress((void**)&xq_lo, g_xq_lo);
    cudaGetSymbolAddress((void**)&xk_hi, g_xk_hi); cudaGetSymbolAddress((void**)&xk_lo, g_xk_lo);
    cudaGetSymbolAddress((void**)&xv_hi, g_xv_hi);
    cudaGetSymbolAddress((void**)&wq_hi, g_wq_hi); cudaGetSymbolAddress((void**)&wq_lo, g_wq_lo);
    cudaGetSymbolAddress((void**)&wk_hi, g_wk_hi); cudaGetSymbolAddress((void**)&wk_lo, g_wk_lo);
    cudaGetSymbolAddress((void**)&wv_hi, g_wv_hi); cudaGetSymbolAddress((void**)&wv_lo, g_wv_lo);
    cudaGetSymbolAddress((void**)&q_hi,  g_q_hi);  cudaGetSymbolAddress((void**)&q_lo,  g_q_lo);
    cudaGetSymbolAddress((void**)&k_hi,  g_k_hi);  cudaGetSymbolAddress((void**)&k_lo,  g_k_lo);
    cudaGetSymbolAddress((void**)&vt,    g_vt);
    cudaGetSymbolAddress((void**)&attn,  g_attn);
    cudaGetSymbolAddress((void**)&sc,    g_scores);

    cudaFuncSetAttribute(mma_gemm<3, 1, 1>, cudaFuncAttributeMaxDynamicSharedMemorySize, NS * StgB<3>::v);
    cudaFuncSetAttribute(mma_gemm<2, 2, 2>, cudaFuncAttributeMaxDynamicSharedMemorySize, NS * StgB<2>::v);
    cudaFuncSetAttribute(mma_gemm<3, 0, 0>, cudaFuncAttributeMaxDynamicSharedMemorySize, NS * StgB<3>::v);
    cudaFuncSetAttribute(mma_gemm<1, 0, 0>, cudaFuncAttributeMaxDynamicSharedMemorySize, NS * StgB<1>::v);

    const long long nIn = (long long)BB * SS * EE;
    const long long nW  = (long long)EE * EE;
    const long long strideQ = (long long)SS * EE;
    const long long strideS = (long long)SS * SS;
    const long long strideVT = (long long)EE * SS;

    // 1) splits / converts
    split2_kernel<<<(int)(nIn / 4 / 256), 256>>>((const float4*)query, (uint2*)xq_hi, (uint2*)xq_lo, (int)(nIn / 4));
    split2_kernel<<<(int)(nIn / 4 / 256), 256>>>((const float4*)key,   (uint2*)xk_hi, (uint2*)xk_lo, (int)(nIn / 4));
    cvt1_kernel<<<(int)(nIn / 4 / 256), 256>>>((const float4*)value, (uint2*)xv_hi, (int)(nIn / 4));
    split2_kernel<<<(int)(nW / 4 / 256), 256>>>((const float4*)Wq, (uint2*)wq_hi, (uint2*)wq_lo, (int)(nW / 4));
    split2_kernel<<<(int)(nW / 4 / 256), 256>>>((const float4*)Wk, (uint2*)wk_hi, (uint2*)wk_lo, (int)(nW / 4));
    split2_kernel<<<(int)(nW / 4 / 256), 256>>>((const float4*)Wv, (uint2*)wv_hi, (uint2*)wv_lo, (int)(nW / 4));

    // 2) q/k projections (3-term, split fp16 out, per-N bias)
    {
        dim3 g(EE / 128, (BB * SS) / 128, 1);
        mma_gemm<3, 1, 1><<<g, 256, NS * StgB<3>::v>>>(xq_hi, xq_lo, wq_hi, wq_lo, bq,
                                                       nullptr, q_hi, q_lo,
                                                       BB * SS, EE, EE, 0, 0, 0);
        mma_gemm<3, 1, 1><<<g, 256, NS * StgB<3>::v>>>(xk_hi, xk_lo, wk_hi, wk_lo, bk,
                                                       nullptr, k_hi, k_lo,
                                                       BB * SS, EE, EE, 0, 0, 0);
    }

    // 3) v projection, transposed (2-term: Wv split x value single; fp16 out; per-M bias)
    {
        dim3 g(SS / 128, EE / 128, BB);
        mma_gemm<2, 2, 2><<<g, 256, NS * StgB<2>::v>>>(wv_hi, wv_lo, xv_hi, nullptr, bv,
                                                       nullptr, vt, nullptr,
                                                       EE, SS, EE, 0, strideQ, strideVT);
    }

    // 4) scores = q @ k^T (3-term, fp32 out)
    {
        dim3 g(SS / 128, SS / 128, BB);
        mma_gemm<3, 0, 0><<<g, 256, NS * StgB<3>::v>>>(q_hi, q_lo, k_hi, k_lo, nullptr,
                                                       sc, nullptr, nullptr,
                                                       SS, SS, EE, strideQ, strideQ, strideS);
    }

    // 5) softmax -> fp16 attn
    softmax_kernel<<<BB * SS, 256>>>(sc, attn);

    // 6) out = attn @ vt^T (1-term, fp32 out)
    {
        dim3 g(EE / 128, SS / 128, BB);
        mma_gemm<1, 0, 0><<<g, 256, NS * StgB<1>::v>>>(attn, nullptr, vt, nullptr, nullptr,
                                                       out, nullptr, nullptr,
                                                       SS, EE, SS, strideS, strideVT, strideQ);
    }
}